// round 10
// baseline (speedup 1.0000x reference)
#include <cuda_runtime.h>
#include <cuda_bf16.h>
#include <math_constants.h>

// BBOX_XFORM_CLIP = log(1000/16)
#define BBOX_XFORM_CLIP 4.135166556742356f

#define HALF_ROWS 4                  // rows per half-tile (one row per warp)
#define ROWS_PER_BLOCK (2 * HALF_ROWS)
#define THREADS 128                  // 4 warps

#define BOX_HALF_BYTES (HALF_ROWS * 81 * 16)   // 5184
#define SC_HALF_BYTES  (HALF_ROWS * 81 * 4)    // 1296
#define LOG_BLK_BYTES  (ROWS_PER_BLOCK * 81 * 4)   // 2592 (16B-aligned blocks)
#define PR_BLK_BYTES   (ROWS_PER_BLOCK * 16)       // 128
#define TX_BYTES (LOG_BLK_BYTES + 2 * PR_BLK_BYTES) // 2848

// img dims may arrive as int32 or float32; disambiguate by plausibility.
__device__ __forceinline__ float load_dim(const void* p) {
    int iv = *(const int*)p;
    if (iv > 0 && iv < (1 << 20)) return (float)iv;
    return __int_as_float(iv);
}

struct RowOut {
    float4 box;
    float sc0, sc1, sc2;
};

// shared-memory-input row processing (main path)
__device__ __forceinline__ RowOut process_row_smem(
    const float* __restrict__ s_log,   // [8*81] logits for this CTA
    const float4* __restrict__ s_pr,   // [8]
    const float4* __restrict__ s_rg,   // [8]
    int lr, int lane, float wmax, float hmax)
{
    const float* lrow = s_log + lr * 81;
    float v0 = lrow[lane];
    float v1 = lrow[lane + 32];
    float v2 = (lane < 17) ? lrow[lane + 64] : -CUDART_INF_F;
    const float4 b  = s_pr[lr];
    const float4 rc = s_rg[lr];

    // ---------------- softmax over 81 logits ----------------
    float m = fmaxf(fmaxf(v0, v1), v2);
    #pragma unroll
    for (int o = 16; o; o >>= 1)
        m = fmaxf(m, __shfl_xor_sync(0xffffffffu, m, o));

    float e0 = __expf(v0 - m);
    float e1 = __expf(v1 - m);
    float e2 = (lane < 17) ? __expf(v2 - m) : 0.0f;

    float s = e0 + e1 + e2;
    #pragma unroll
    for (int o = 16; o; o >>= 1)
        s += __shfl_xor_sync(0xffffffffu, s, o);
    const float inv = __fdividef(1.0f, s);

    // ---------------- bbox decode (all lanes redundantly) ----------------
    const float w  = b.z - b.x + 1.0f;
    const float h  = b.w - b.y + 1.0f;
    const float cx = b.x + 0.5f * w;
    const float cy = b.y + 0.5f * h;

    const float dx = rc.x * 0.1f;
    const float dy = rc.y * 0.1f;
    const float dw = fminf(rc.z * 0.2f, BBOX_XFORM_CLIP);
    const float dh = fminf(rc.w * 0.2f, BBOX_XFORM_CLIP);

    const float pcx = dx * w + cx;
    const float pcy = dy * h + cy;
    const float pw  = __expf(dw) * w;
    const float ph  = __expf(dh) * h;

    float x1 = pcx - 0.5f * pw;
    float y1 = pcy - 0.5f * ph;
    float x2 = pcx + 0.5f * pw - 1.0f;
    float y2 = pcy + 0.5f * ph - 1.0f;

    RowOut r;
    r.box = make_float4(fminf(fmaxf(x1, 0.0f), wmax),
                        fminf(fmaxf(y1, 0.0f), hmax),
                        fminf(fmaxf(x2, 0.0f), wmax),
                        fminf(fmaxf(y2, 0.0f), hmax));
    r.sc0 = e0 * inv;
    r.sc1 = e1 * inv;
    r.sc2 = e2 * inv;
    return r;
}

// global-memory-input variant (tail path only)
__device__ __forceinline__ RowOut process_row_gmem(
    const float* __restrict__ logits,
    const float* __restrict__ regr,
    const float* __restrict__ prop,
    int n, int lane, float wmax, float hmax)
{
    const float4 b  = reinterpret_cast<const float4*>(prop)[n];
    const float4 rc = reinterpret_cast<const float4*>(regr)[n];
    const float* lrow = logits + (size_t)n * 81;
    float v0 = lrow[lane];
    float v1 = lrow[lane + 32];
    float v2 = (lane < 17) ? lrow[lane + 64] : -CUDART_INF_F;

    float m = fmaxf(fmaxf(v0, v1), v2);
    #pragma unroll
    for (int o = 16; o; o >>= 1)
        m = fmaxf(m, __shfl_xor_sync(0xffffffffu, m, o));
    float e0 = __expf(v0 - m);
    float e1 = __expf(v1 - m);
    float e2 = (lane < 17) ? __expf(v2 - m) : 0.0f;
    float s = e0 + e1 + e2;
    #pragma unroll
    for (int o = 16; o; o >>= 1)
        s += __shfl_xor_sync(0xffffffffu, s, o);
    const float inv = __fdividef(1.0f, s);

    const float w  = b.z - b.x + 1.0f;
    const float h  = b.w - b.y + 1.0f;
    const float cx = b.x + 0.5f * w;
    const float cy = b.y + 0.5f * h;
    const float dx = rc.x * 0.1f;
    const float dy = rc.y * 0.1f;
    const float dw = fminf(rc.z * 0.2f, BBOX_XFORM_CLIP);
    const float dh = fminf(rc.w * 0.2f, BBOX_XFORM_CLIP);
    const float pcx = dx * w + cx;
    const float pcy = dy * h + cy;
    const float pw  = __expf(dw) * w;
    const float ph  = __expf(dh) * h;
    RowOut r;
    r.box = make_float4(fminf(fmaxf(pcx - 0.5f * pw, 0.0f), wmax),
                        fminf(fmaxf(pcy - 0.5f * ph, 0.0f), hmax),
                        fminf(fmaxf(pcx + 0.5f * pw - 1.0f, 0.0f), wmax),
                        fminf(fmaxf(pcy + 0.5f * ph - 1.0f, 0.0f), hmax));
    r.sc0 = e0 * inv;
    r.sc1 = e1 * inv;
    r.sc2 = e2 * inv;
    return r;
}

__device__ __forceinline__ void stage_row(float* s_box, float* s_sc,
                                          int lr, int lane, const RowOut& r)
{
    float4* sb = reinterpret_cast<float4*>(s_box) + lr * 81;
    sb[lane]      = r.box;
    sb[lane + 32] = r.box;
    if (lane < 17) sb[lane + 64] = r.box;

    float* ss = s_sc + lr * 81;
    ss[lane]      = r.sc0;
    ss[lane + 32] = r.sc1;
    if (lane < 17) ss[lane + 64] = r.sc2;
}

__device__ __forceinline__ void commit_half(const float* s_box, const float* s_sc,
                                            float* boxes_out, float* scores_out,
                                            long long half_idx)
{
    asm volatile("fence.proxy.async.shared::cta;" ::: "memory");
    unsigned sb_a = (unsigned)__cvta_generic_to_shared(s_box);
    unsigned ss_a = (unsigned)__cvta_generic_to_shared(s_sc);
    char* gb = (char*)boxes_out  + (size_t)half_idx * BOX_HALF_BYTES;
    char* gs = (char*)scores_out + (size_t)half_idx * SC_HALF_BYTES;
    asm volatile("cp.async.bulk.global.shared::cta.bulk_group [%0], [%1], %2;"
                 :: "l"(gb), "r"(sb_a), "n"(BOX_HALF_BYTES) : "memory");
    asm volatile("cp.async.bulk.global.shared::cta.bulk_group [%0], [%1], %2;"
                 :: "l"(gs), "r"(ss_a), "n"(SC_HALF_BYTES) : "memory");
    asm volatile("cp.async.bulk.commit_group;" ::: "memory");
}

__global__ void __launch_bounds__(THREADS)
postproc_kernel(const float* __restrict__ logits,       // [N,81]
                const float* __restrict__ regr,         // [N,4]
                const float* __restrict__ prop,         // [N,4]
                const void*  __restrict__ imw_p,
                const void*  __restrict__ imh_p,
                float* __restrict__ boxes_out,          // [N*81,4]
                float* __restrict__ scores_out,         // [N*81]
                int N)
{
    __shared__ alignas(16) float  s_log[ROWS_PER_BLOCK * 81];   // 2592 B
    __shared__ alignas(16) float4 s_pr [ROWS_PER_BLOCK];        //  128 B
    __shared__ alignas(16) float4 s_rg [ROWS_PER_BLOCK];        //  128 B
    __shared__ alignas(16) float  s_box[2][HALF_ROWS * 81 * 4]; // 2x5184 B
    __shared__ alignas(16) float  s_sc [2][HALF_ROWS * 81];     // 2x1296 B
    __shared__ alignas(8)  unsigned long long s_mbar;

    const int warp = threadIdx.x >> 5;
    const int lane = threadIdx.x & 31;
    const int r0   = blockIdx.x * ROWS_PER_BLOCK;

    const float wmax = load_dim(imw_p) - 1.0f;
    const float hmax = load_dim(imh_p) - 1.0f;

    if (r0 + ROWS_PER_BLOCK <= N) {
        const unsigned mb = (unsigned)__cvta_generic_to_shared(&s_mbar);

        // -------- prologue: init mbar, then one-shot bulk load of all inputs
        if (threadIdx.x == 0) {
            asm volatile("mbarrier.init.shared.b64 [%0], 1;" :: "r"(mb) : "memory");
            asm volatile("fence.proxy.async.shared::cta;" ::: "memory");
        }
        __syncthreads();
        if (threadIdx.x == 0) {
            asm volatile("mbarrier.arrive.expect_tx.shared::cta.b64 _, [%0], %1;"
                         :: "r"(mb), "n"(TX_BYTES) : "memory");
            unsigned dl = (unsigned)__cvta_generic_to_shared(s_log);
            unsigned dp = (unsigned)__cvta_generic_to_shared(s_pr);
            unsigned dr = (unsigned)__cvta_generic_to_shared(s_rg);
            const char* gl = (const char*)logits + (size_t)blockIdx.x * LOG_BLK_BYTES;
            const char* gp = (const char*)prop   + (size_t)blockIdx.x * PR_BLK_BYTES;
            const char* gr = (const char*)regr   + (size_t)blockIdx.x * PR_BLK_BYTES;
            asm volatile("cp.async.bulk.shared::cta.global.mbarrier::complete_tx::bytes "
                         "[%0], [%1], %2, [%3];"
                         :: "r"(dl), "l"(gl), "n"(LOG_BLK_BYTES), "r"(mb) : "memory");
            asm volatile("cp.async.bulk.shared::cta.global.mbarrier::complete_tx::bytes "
                         "[%0], [%1], %2, [%3];"
                         :: "r"(dp), "l"(gp), "n"(PR_BLK_BYTES), "r"(mb) : "memory");
            asm volatile("cp.async.bulk.shared::cta.global.mbarrier::complete_tx::bytes "
                         "[%0], [%1], %2, [%3];"
                         :: "r"(dr), "l"(gr), "n"(PR_BLK_BYTES), "r"(mb) : "memory");
        }
        // all threads wait for inputs (phase 0)
        asm volatile(
            "{\n\t"
            ".reg .pred P;\n"
            "W%=:\n\t"
            "mbarrier.try_wait.parity.acquire.cta.shared::cta.b64 P, [%0], 0, 0x989680;\n\t"
            "@!P bra W%=;\n\t"
            "}"
            :: "r"(mb) : "memory");

        // ---------------- half A ----------------
        {
            RowOut r = process_row_smem(s_log, s_pr, s_rg, warp, lane, wmax, hmax);
            stage_row(s_box[0], s_sc[0], warp, lane, r);
        }
        __syncthreads();
        if (threadIdx.x == 0)
            commit_half(s_box[0], s_sc[0], boxes_out, scores_out,
                        2LL * blockIdx.x);          // no wait: drains under half B

        // ---------------- half B (overlaps half A's drain) ----------------
        {
            RowOut r = process_row_smem(s_log, s_pr, s_rg, HALF_ROWS + warp,
                                        lane, wmax, hmax);
            stage_row(s_box[1], s_sc[1], warp, lane, r);
        }
        __syncthreads();
        if (threadIdx.x == 0) {
            commit_half(s_box[1], s_sc[1], boxes_out, scores_out,
                        2LL * blockIdx.x + 1);
            // CTA must stay alive until the bulk engine has read both buffers
            asm volatile("cp.async.bulk.wait_group.read 0;" ::: "memory");
        }
    } else {
        // partial tail tile (not hit when N % 8 == 0): direct gmem path
        #pragma unroll
        for (int i = 0; i < 2; i++) {
            const int n = r0 + i * HALF_ROWS + warp;
            if (n >= N) break;
            RowOut r = process_row_gmem(logits, regr, prop, n, lane, wmax, hmax);
            float4* bo = reinterpret_cast<float4*>(boxes_out) + (size_t)n * 81;
            bo[lane]      = r.box;
            bo[lane + 32] = r.box;
            if (lane < 17) bo[lane + 64] = r.box;
            float* so = scores_out + (size_t)n * 81;
            so[lane]      = r.sc0;
            so[lane + 32] = r.sc1;
            if (lane < 17) so[lane + 64] = r.sc2;
        }
    }
}

extern "C" void kernel_launch(void* const* d_in, const int* in_sizes, int n_in,
                              void* d_out, int out_size) {
    const float* logits = (const float*)d_in[0];
    const float* regr   = (const float*)d_in[1];
    const float* prop   = (const float*)d_in[2];
    const void*  imw    = d_in[3];
    const void*  imh    = d_in[4];

    const int N = in_sizes[0] / 81;          // 262144

    float* boxes  = (float*)d_out;           // N*81*4 floats
    float* scores = boxes + (size_t)N * 81 * 4;

    const int blocks = (N + ROWS_PER_BLOCK - 1) / ROWS_PER_BLOCK;  // 32768
    postproc_kernel<<<blocks, THREADS>>>(logits, regr, prop, imw, imh,
                                         boxes, scores, N);
}